// round 13
// baseline (speedup 1.0000x reference)
#include <cuda_runtime.h>
#include <cuda_bf16.h>
#include <cstdint>

#define C_CLS   19
#define V_VIEWS 10
#define NQ      38
#define QS      8192
#define M_TOT   (NQ*QS)
#define N_ROWS  190
#define N_PAD   192
#define INV_T   (1.0f/0.07f)
#define L2E     1.44269504f

#define CHUNKS      152               // column chunks of 2048
#define CTA_COLS    2048
#define ROWS_CTA    96                // anchor rows per CTA (2 halves)
#define TILE_COLS   32
#define TILES       (CTA_COLS / TILE_COLS)   // 64
#define GRID1       (CHUNKS * 2)      // 304 CTAs

// packed A: [rowgrp(6)][kk(16)][lane(32)][4 words]  (one LDS.128 per fragment)
#define A_WORDS     (6*16*32*4)       // 12288 u32 = 48 KB
#define SB          132               // B row pitch in u32 (128 data + 4 pad)
#define B_WORDS     (TILE_COLS*SB)    // 4224 u32 = 16.5 KB
#define STATS_F     (4*ROWS_CTA)      // per-wn partials
#define SMEM_BYTES  ((A_WORDS + 2*B_WORDS)*4 + 2*STATS_F*4)   // 84 KB

__device__ float g_P[N_PAD * QS];
__device__ float g_mxPart[N_PAD * CHUNKS];
__device__ float g_sPart [N_PAD * CHUNKS];
__device__ float g_mlpp[N_PAD];

__device__ __forceinline__ float fexp2(float x) {
    float y; asm("ex2.approx.ftz.f32 %0, %1;" : "=f"(y) : "f"(x)); return y;
}
__device__ __forceinline__ uint32_t pack_bf16(float x, float y) {
    uint16_t lo = __bfloat16_as_ushort(__float2bfloat16(x));
    uint16_t hi = __bfloat16_as_ushort(__float2bfloat16(y));
    return ((uint32_t)hi << 16) | (uint32_t)lo;
}
__device__ __forceinline__ void mma_bf16(float& d0, float& d1, float& d2, float& d3,
                                         uint32_t a0, uint32_t a1, uint32_t a2, uint32_t a3,
                                         uint32_t b0, uint32_t b1) {
    asm("mma.sync.aligned.m16n8k16.row.col.f32.bf16.bf16.f32 "
        "{%0,%1,%2,%3}, {%4,%5,%6,%7}, {%8,%9}, {%0,%1,%2,%3};\n"
        : "+f"(d0), "+f"(d1), "+f"(d2), "+f"(d3)
        : "r"(a0), "r"(a1), "r"(a2), "r"(a3), "r"(b0), "r"(b1));
}
__device__ __forceinline__ void upd_ms(float& m, float& s, float d) {
    if (d > m) { s = s * fexp2((m - d) * L2E) + 1.0f; m = d; }
    else if (d - m > -30.0f) { s += fexp2((d - m) * L2E); }
}
__device__ __forceinline__ void merge_ms(float& m, float& s, float mo, float so) {
    float nm = fmaxf(m, mo);
    s = s * fexp2((m - nm) * L2E) + so * fexp2((mo - nm) * L2E);
    m = nm;
}

// ============ Kernel 1: fused bf16-MMA GEMM + online neg (max,sumexp) ============
// grid = 304 (152 chunks x 2 anchor halves), 256 threads, 2 CTAs/SM
__global__ void __launch_bounds__(256, 2)
gemm_stats_kernel(const float* __restrict__ feat,
                  const int*   __restrict__ label,
                  const float* __restrict__ queue)
{
    extern __shared__ uint32_t sm[];
    uint32_t* AsP   = sm;                         // packed A fragments
    uint32_t* BsU   = sm + A_WORDS;               // 2-stage B
    float*    sm_mx = (float*)(sm + A_WORDS + 2*B_WORDS);
    float*    sm_s  = sm_mx + STATS_F;
    __shared__ int s_lab[C_CLS];

    const int tid   = threadIdx.x;
    const int lane  = tid & 31;
    const int warp  = tid >> 5;
    const int wm    = warp & 1;       // 2 m-warps (48 rows each)
    const int wn    = warp >> 1;      // 4 n-warps (8 cols each)
    const int g     = lane >> 2;
    const int tig   = lane & 3;
    const int bid   = blockIdx.x;
    const int chunk = bid >> 1;
    const int half  = bid & 1;
    const int q     = chunk >> 2;     // queue row/class of this chunk
    const int col0  = chunk * CTA_COLS;
    const int row0  = half * ROWS_CTA;

    if (tid < C_CLS) s_lab[tid] = label[tid];

    // ---- fill packed A: As[rg][kk][lane][j] = feat/T as bf16 pairs ----
    {
        const float2* f2 = (const float2*)feat;
        for (int i = tid; i < ROWS_CTA * 128; i += 256) {
            int r = i >> 7, w = i & 127;         // local row, u32-word (2 k each)
            int n = row0 + r;
            uint32_t val = 0u;
            if (n < N_ROWS) {
                int cc = n % C_CLS, vv = n / C_CLS;
                float2 x = f2[(cc * V_VIEWS + vv) * 128 + w];
                val = pack_bf16(x.x * INV_T, x.y * INV_T);
            }
            int rg = r >> 4, rr = r & 15;
            int gg = rr & 7, hh = rr >> 3;
            int kk = w >> 3, ww = w & 7;
            int tg = ww & 3, hf = ww >> 2;
            AsP[((((rg * 16 + kk) * 32) + gg * 4 + tg) << 2) + hh + 2 * hf] = val;
        }
    }

    // ---- B staging map: thread -> (col = tid>>3, 128B segment = tid&7) ----
    const int bcol = tid >> 3;
    const int bseg = tid & 7;
    const float4* q4 = (const float4*)queue;

    float4 st[8];
    #pragma unroll
    for (int i = 0; i < 8; i++)
        st[i] = q4[(size_t)(col0 + bcol) * 64 + bseg * 8 + i];
    {
        uint4* bw = (uint4*)(BsU + bcol * SB + bseg * 16);
        #pragma unroll
        for (int i = 0; i < 4; i++) {
            uint4 w;
            w.x = pack_bf16(st[2*i].x,   st[2*i].y);
            w.y = pack_bf16(st[2*i].z,   st[2*i].w);
            w.z = pack_bf16(st[2*i+1].x, st[2*i+1].y);
            w.w = pack_bf16(st[2*i+1].z, st[2*i+1].w);
            bw[i] = w;
        }
    }
    __syncthreads();

    // ---- per-lane slots: 6 rows per lane (mi 0..2, h 0..1) ----
    float mx6[6], s6[6];
    bool  posS[6];
    int   rowL[6];
    #pragma unroll
    for (int s = 0; s < 6; s++) {
        int mi = s >> 1, h = s & 1;
        int rl = wm * 48 + mi * 16 + g + h * 8;
        rowL[s] = rl;
        posS[s] = (s_lab[(row0 + rl) % C_CLS] == q);
        mx6[s] = -1e30f; s6[s] = 0.0f;
    }

    const uint32_t apBase = (wm * 3) * 16 * 32 * 4 + lane * 4;

    for (int t = 0; t < TILES; t++) {
        const int  cur     = t & 1;
        const bool hasNext = (t + 1 < TILES);

        if (hasNext) {
            #pragma unroll
            for (int i = 0; i < 8; i++)
                st[i] = q4[(size_t)(col0 + (t + 1) * TILE_COLS + bcol) * 64 + bseg * 8 + i];
        }

        float acc[3][4];
        #pragma unroll
        for (int mi = 0; mi < 3; mi++)
            #pragma unroll
            for (int v = 0; v < 4; v++) acc[mi][v] = 0.0f;

        const uint32_t* pb = BsU + cur * B_WORDS + (wn * 8 + g) * SB + tig;

        #pragma unroll
        for (int kk = 0; kk < 16; kk++) {
            uint32_t b0 = pb[kk * 8];
            uint32_t b1 = pb[kk * 8 + 4];
            #pragma unroll
            for (int mi = 0; mi < 3; mi++) {
                uint4 a = *(const uint4*)(AsP + apBase + (mi * 16 + kk) * 128);
                mma_bf16(acc[mi][0], acc[mi][1], acc[mi][2], acc[mi][3],
                         a.x, a.y, a.z, a.w, b0, b1);
            }
        }

        if (hasNext) {
            uint4* bw = (uint4*)(BsU + (cur ^ 1) * B_WORDS + bcol * SB + bseg * 16);
            #pragma unroll
            for (int i = 0; i < 4; i++) {
                uint4 w;
                w.x = pack_bf16(st[2*i].x,   st[2*i].y);
                w.y = pack_bf16(st[2*i].z,   st[2*i].w);
                w.z = pack_bf16(st[2*i+1].x, st[2*i+1].y);
                w.w = pack_bf16(st[2*i+1].z, st[2*i+1].w);
                bw[i] = w;
            }
        }

        // epilogue: positives -> g_P; negatives -> running (max, sumexp)
        const int colB = (chunk & 3) * CTA_COLS + t * TILE_COLS + wn * 8 + tig * 2;
        #pragma unroll
        for (int s = 0; s < 6; s++) {
            const int mi = s >> 1, h = s & 1;
            if (posS[s]) {
                const int nglob = row0 + rowL[s];
                *(float2*)(g_P + (size_t)nglob * QS + colB) =
                    make_float2(acc[mi][h * 2], acc[mi][h * 2 + 1]);
            } else {
                upd_ms(mx6[s], s6[s], acc[mi][h * 2]);
                upd_ms(mx6[s], s6[s], acc[mi][h * 2 + 1]);
            }
        }
        __syncthreads();
    }

    // ---- reduce stats: quad (tig) -> smem per wn -> merge 4 wn -> global ----
    #pragma unroll
    for (int s = 0; s < 6; s++) {
        #pragma unroll
        for (int off = 1; off <= 2; off <<= 1) {
            float mo = __shfl_xor_sync(0xffffffffu, mx6[s], off);
            float so = __shfl_xor_sync(0xffffffffu, s6[s], off);
            merge_ms(mx6[s], s6[s], mo, so);
        }
    }
    if (tig == 0) {
        #pragma unroll
        for (int s = 0; s < 6; s++) {
            sm_mx[wn * ROWS_CTA + rowL[s]] = mx6[s];
            sm_s [wn * ROWS_CTA + rowL[s]] = s6[s];
        }
    }
    __syncthreads();
    if (tid < ROWS_CTA) {
        float m = sm_mx[tid], ss = sm_s[tid];
        #pragma unroll
        for (int wnn = 1; wnn < 4; wnn++)
            merge_ms(m, ss, sm_mx[wnn * ROWS_CTA + tid], sm_s[wnn * ROWS_CTA + tid]);
        g_mxPart[(size_t)(row0 + tid) * CHUNKS + chunk] = m;
        g_sPart [(size_t)(row0 + tid) * CHUNKS + chunk] = ss;
    }
}

// ============ Kernel 2: per-row merge partials + positive-term sums ============
__global__ void __launch_bounds__(256)
pass2_kernel(const int* __restrict__ label)
{
    __shared__ float  rm[256], rs[256];
    __shared__ double rd1[256], rd2[256];
    const int n = blockIdx.x;
    const int t = threadIdx.x;
    const int cval = label[n % C_CLS];

    float m = -1e30f, s = 0.0f;
    if (t < CHUNKS) { m = g_mxPart[(size_t)n * CHUNKS + t]; s = g_sPart[(size_t)n * CHUNKS + t]; }
    rm[t] = m; rs[t] = s;
    __syncthreads();
    for (int off = 128; off > 0; off >>= 1) {
        if (t < off) {
            float mm = rm[t], sv = rs[t];
            merge_ms(mm, sv, rm[t + off], rs[t + off]);
            rm[t] = mm; rs[t] = sv;
        }
        __syncthreads();
    }
    const float MX = rm[0], S = rs[0];
    const float logS = __logf(S);

    double t1 = 0.0, t2 = 0.0;
    const float* Pr = g_P + (size_t)n * QS;
    for (int j = t; j < QS; j += 256) {
        if (cval == 0 && j == n) continue;       // self-contrast removal
        float x = Pr[j] - MX;
        t1 += (double)x;
        float term;
        if (x > 80.0f)             term = x;
        else if (x < logS - 15.0f) term = logS;
        else                       term = __logf(__expf(x) + S);
        t2 += (double)term;
    }
    rd1[t] = t1; rd2[t] = t2;
    __syncthreads();
    for (int off = 128; off > 0; off >>= 1) {
        if (t < off) { rd1[t] += rd1[t + off]; rd2[t] += rd2[t + off]; }
        __syncthreads();
    }
    if (t == 0) {
        double Pn = (cval == 0) ? (double)(QS - 1) : (double)QS;
        g_mlpp[n] = (float)((rd1[0] - rd2[0]) / Pn);
    }
}

// ============ Kernel 3: final scalar ============
__global__ void pass3_kernel(float* __restrict__ out)
{
    __shared__ double r[64];
    int t = threadIdx.x;
    double v = 0.0;
    for (int i = t; i < N_ROWS; i += 64) v += (double)g_mlpp[i];
    r[t] = v; __syncthreads();
    for (int off = 32; off > 0; off >>= 1) {
        if (t < off) r[t] += r[t + off];
        __syncthreads();
    }
    if (t == 0) out[0] = (float)(-(r[0] / (double)N_ROWS) * 0.5);
}

extern "C" void kernel_launch(void* const* d_in, const int* in_sizes, int n_in,
                              void* d_out, int out_size)
{
    const float* feat  = (const float*)d_in[0];
    const int*   label = (const int*)d_in[1];
    const float* queue = (const float*)d_in[2];
    float* out = (float*)d_out;

    cudaFuncSetAttribute(gemm_stats_kernel,
                         cudaFuncAttributeMaxDynamicSharedMemorySize, SMEM_BYTES);
    gemm_stats_kernel<<<GRID1, 256, SMEM_BYTES>>>(feat, label, queue);
    pass2_kernel<<<N_ROWS, 256>>>(label);
    pass3_kernel<<<1, 64>>>(out);
}

// round 14
// speedup vs baseline: 1.2916x; 1.2916x over previous
#include <cuda_runtime.h>
#include <cuda_bf16.h>
#include <cstdint>

#define C_CLS   19
#define V_VIEWS 10
#define NQ      38
#define QS      8192
#define M_TOT   (NQ*QS)
#define N_ROWS  190
#define N_PAD   192
#define INV_T   (1.0f/0.07f)
#define L2E     1.44269504f

#define PAIRS       148
#define GRID1       (PAIRS*2)            // 296 CTAs = exactly one wave @ 2 CTAs/SM
#define TILE_COLS   64
#define TOT_TILES   (M_TOT / TILE_COLS)  // 4864
#define ROWS_CTA    96

// packed A: [rg(6)][kk(16)][lane(32)][4 words] -> 12288 u32 = 48 KB
#define A_WORDS     (6*16*32*4)
// packed B half-stage: [cg(8)][kh(8)][lane(32)][2 words] -> 4096 u32 = 16 KB
#define BSTG_WORDS  (8*8*32*2)
#define SMEM_BYTES  ((A_WORDS + 2*BSTG_WORDS)*4)   // 81920 B

__device__ float g_P[N_PAD * QS];
__device__ float g_mxPart[N_PAD * PAIRS];
__device__ float g_sPart [N_PAD * PAIRS];
__device__ float g_mlpp[N_PAD];

__device__ __forceinline__ float fexp2(float x) {
    float y; asm("ex2.approx.ftz.f32 %0, %1;" : "=f"(y) : "f"(x)); return y;
}
// returns bf16x2 word: lo = lo-arg, hi = hi-arg
__device__ __forceinline__ uint32_t pack2(float lo, float hi) {
    uint32_t r; asm("cvt.rn.bf16x2.f32 %0, %1, %2;" : "=r"(r) : "f"(hi), "f"(lo)); return r;
}
__device__ __forceinline__ void mma_bf16(float& d0, float& d1, float& d2, float& d3,
                                         uint32_t a0, uint32_t a1, uint32_t a2, uint32_t a3,
                                         uint32_t b0, uint32_t b1) {
    asm("mma.sync.aligned.m16n8k16.row.col.f32.bf16.bf16.f32 "
        "{%0,%1,%2,%3}, {%4,%5,%6,%7}, {%8,%9}, {%0,%1,%2,%3};\n"
        : "+f"(d0), "+f"(d1), "+f"(d2), "+f"(d3)
        : "r"(a0), "r"(a1), "r"(a2), "r"(a3), "r"(b0), "r"(b1));
}
__device__ __forceinline__ void upd_ms(float& m, float& s, float d) {
    if (d > m) { s = s * fexp2((m - d) * L2E) + 1.0f; m = d; }
    else if (d - m > -30.0f) { s += fexp2((d - m) * L2E); }
}
__device__ __forceinline__ void merge_ms(float& m, float& s, float mo, float so) {
    float nm = fmaxf(m, mo);
    s = s * fexp2((m - nm) * L2E) + so * fexp2((mo - nm) * L2E);
    m = nm;
}

// packed-A word index for local row r (0..95), k-pair word w (0..127)
__device__ __forceinline__ int a_addr(int r, int w) {
    int rg = r >> 4, rr = r & 15;
    int kk = w >> 3, ww = w & 7;
    int lane = (rr & 7) * 4 + (ww & 3);
    int j = (rr >> 3) + 2 * (ww >> 2);
    return ((rg * 16 + kk) * 32 + lane) * 4 + j;
}

// store one staged half (64 floats = this thread's (col, 4 kh-slices)) into packed B
__device__ __forceinline__ void sts_half(uint32_t* Bst, const float4 st[16],
                                         int c, int part) {
    const int cg = c >> 3;
    const int xbit = (c >> 2) & 1;
    const int crow = (c & 7) * 2;
    #pragma unroll
    for (int j = 0; j < 4; j++) {
        int kh = part * 4 + j;
        uint32_t base = (uint32_t)(cg * 8 + kh) * 64;
        uint32_t u0 = pack2(st[j*4+0].x, st[j*4+0].y);
        uint32_t u1 = pack2(st[j*4+2].x, st[j*4+2].y);
        uint32_t u2 = pack2(st[j*4+0].z, st[j*4+0].w);
        uint32_t u3 = pack2(st[j*4+2].z, st[j*4+2].w);
        uint32_t u4 = pack2(st[j*4+1].x, st[j*4+1].y);
        uint32_t u5 = pack2(st[j*4+3].x, st[j*4+3].y);
        uint32_t u6 = pack2(st[j*4+1].z, st[j*4+1].w);
        uint32_t u7 = pack2(st[j*4+3].z, st[j*4+3].w);
        *(uint4*)(Bst + base + (uint32_t)(((crow + 0) ^ xbit) << 2)) = make_uint4(u0,u1,u2,u3);
        *(uint4*)(Bst + base + (uint32_t)(((crow + 1) ^ xbit) << 2)) = make_uint4(u4,u5,u6,u7);
    }
}

// ============ Kernel 1: fused bf16-MMA GEMM + online neg (max,sumexp) ============
// grid = 296 (148 pairs x 2 row-halves), 128 threads, 2 CTAs/SM, one wave
__global__ void __launch_bounds__(128, 2)
gemm_stats_kernel(const float* __restrict__ feat,
                  const int*   __restrict__ label,
                  const float* __restrict__ queue)
{
    extern __shared__ uint32_t sm[];
    uint32_t* AsP  = sm;
    uint32_t* Bst0 = sm + A_WORDS;
    uint32_t* Bst1 = sm + A_WORDS + BSTG_WORDS;
    __shared__ int s_lab[C_CLS];

    const int tid  = threadIdx.x;
    const int lane = tid & 31;
    const int warp = tid >> 5;
    const int wm   = warp & 1;         // 2 m-warps (48 rows each)
    const int wn   = warp >> 1;        // 2 n-warps (32 cols each)
    const int g    = lane >> 2;
    const int tig  = lane & 3;
    const int bid  = blockIdx.x;
    const int pair = bid >> 1;
    const int row0 = (bid & 1) * ROWS_CTA;

    if (tid < C_CLS) s_lab[tid] = label[tid];

    // ---- fill packed A: feat/T as bf16 fragments ----
    {
        const float4* f4 = (const float4*)feat;
        for (int i = tid; i < ROWS_CTA * 64; i += 128) {
            int r = i >> 6, wp = i & 63;        // local row, float4 index (4 k)
            int n = row0 + r;
            uint32_t v0 = 0u, v1 = 0u;
            if (n < N_ROWS) {
                int cc = n % C_CLS, vv = n / C_CLS;
                float4 x = f4[(cc * V_VIEWS + vv) * 64 + wp];
                v0 = pack2(x.x * INV_T, x.y * INV_T);
                v1 = pack2(x.z * INV_T, x.w * INV_T);
            }
            AsP[a_addr(r, wp * 2)]     = v0;
            AsP[a_addr(r, wp * 2 + 1)] = v1;
        }
    }

    // ---- staging map: c = col in tile, part = k-quarter within half ----
    const int c    = tid & 63;
    const int part = tid >> 6;
    const float4* q4 = (const float4*)queue;
    const int loff = ((((lane >> 1) ^ ((lane >> 4) & 1)) << 2) + (lane & 1) * 2);

    // ---- per-lane slots ----
    float mx6[6], s6[6];
    int   rowL[6], cls6[6];
    #pragma unroll
    for (int s = 0; s < 6; s++) {
        int mi = s >> 1, h = s & 1;
        int rl = wm * 48 + mi * 16 + g + h * 8;
        rowL[s] = rl;
        cls6[s] = s_lab[(row0 + rl) % C_CLS];
        mx6[s] = -1e30f; s6[s] = 0.0f;
    }

    const int nt = (TOT_TILES - pair + PAIRS - 1) / PAIRS;
    float4 st[16];

    // prologue: stage (tile0, h0) into Bst0
    {
        const float4* p = q4 + ((size_t)(pair * TILE_COLS + c)) * 64 + part * 16;
        #pragma unroll
        for (int i = 0; i < 16; i++) st[i] = p[i];
        sts_half(Bst0, st, c, part);
    }
    __syncthreads();

    int tcur = pair;
    for (int it = 0; it < nt; it++, tcur += PAIRS) {
        const bool lastT = (it + 1 == nt);

        float acc[3][4][4];
        #pragma unroll
        for (int mi = 0; mi < 3; mi++)
            #pragma unroll
            for (int nj = 0; nj < 4; nj++)
                #pragma unroll
                for (int v = 0; v < 4; v++) acc[mi][nj][v] = 0.0f;

        // ===== step h=0: MMA kk 0..7 on Bst0; stage h1 of tcur -> Bst1 =====
        {
            const float4* p = q4 + ((size_t)(tcur * TILE_COLS + c)) * 64 + 32 + part * 16;
            #pragma unroll
            for (int i = 0; i < 16; i++) st[i] = p[i];
        }
        #pragma unroll
        for (int kh = 0; kh < 8; kh++) {
            uint2 b[4];
            #pragma unroll
            for (int nj = 0; nj < 4; nj++)
                b[nj] = *(const uint2*)(Bst0 + ((wn * 4 + nj) * 8 + kh) * 64 + loff);
            #pragma unroll
            for (int mi = 0; mi < 3; mi++) {
                uint4 a = *(const uint4*)(AsP + (((wm * 3 + mi) * 16 + kh) * 32 + lane) * 4);
                #pragma unroll
                for (int nj = 0; nj < 4; nj++)
                    mma_bf16(acc[mi][nj][0], acc[mi][nj][1], acc[mi][nj][2], acc[mi][nj][3],
                             a.x, a.y, a.z, a.w, b[nj].x, b[nj].y);
            }
        }
        sts_half(Bst1, st, c, part);
        __syncthreads();

        // ===== step h=1: MMA kk 8..15 on Bst1; stage h0 of next tile -> Bst0 =====
        if (!lastT) {
            const float4* p = q4 + ((size_t)((tcur + PAIRS) * TILE_COLS + c)) * 64 + part * 16;
            #pragma unroll
            for (int i = 0; i < 16; i++) st[i] = p[i];
        }
        #pragma unroll
        for (int kh = 0; kh < 8; kh++) {
            uint2 b[4];
            #pragma unroll
            for (int nj = 0; nj < 4; nj++)
                b[nj] = *(const uint2*)(Bst1 + ((wn * 4 + nj) * 8 + kh) * 64 + loff);
            #pragma unroll
            for (int mi = 0; mi < 3; mi++) {
                uint4 a = *(const uint4*)(AsP + (((wm * 3 + mi) * 16 + 8 + kh) * 32 + lane) * 4);
                #pragma unroll
                for (int nj = 0; nj < 4; nj++)
                    mma_bf16(acc[mi][nj][0], acc[mi][nj][1], acc[mi][nj][2], acc[mi][nj][3],
                             a.x, a.y, a.z, a.w, b[nj].x, b[nj].y);
            }
        }
        if (!lastT) sts_half(Bst0, st, c, part);

        // ===== epilogue for tile tcur =====
        const int qrow = tcur >> 7;                       // 128 tiles per queue row
        const int cb   = ((tcur & 127) << 6) + wn * 32 + tig * 2;
        #pragma unroll
        for (int s = 0; s < 6; s++) {
            const int mi = s >> 1, h2 = s & 1;
            if (cls6[s] == qrow) {
                float* pp = g_P + (size_t)(row0 + rowL[s]) * QS + cb;
                #pragma unroll
                for (int nj = 0; nj < 4; nj++)
                    *(float2*)(pp + nj * 8) =
                        make_float2(acc[mi][nj][h2 * 2], acc[mi][nj][h2 * 2 + 1]);
            } else {
                #pragma unroll
                for (int nj = 0; nj < 4; nj++) {
                    upd_ms(mx6[s], s6[s], acc[mi][nj][h2 * 2]);
                    upd_ms(mx6[s], s6[s], acc[mi][nj][h2 * 2 + 1]);
                }
            }
        }
        __syncthreads();
    }

    // ---- reduce stats: quad shfl -> smem (aliased over B stages) -> global ----
    #pragma unroll
    for (int s = 0; s < 6; s++) {
        #pragma unroll
        for (int off = 1; off <= 2; off <<= 1) {
            float mo = __shfl_xor_sync(0xffffffffu, mx6[s], off);
            float so = __shfl_xor_sync(0xffffffffu, s6[s], off);
            merge_ms(mx6[s], s6[s], mo, so);
        }
    }
    float* sm_mx = (float*)(sm + A_WORDS);          // 2*96 floats
    float* sm_s  = sm_mx + 2 * ROWS_CTA;
    if (tig == 0) {
        #pragma unroll
        for (int s = 0; s < 6; s++) {
            sm_mx[wn * ROWS_CTA + rowL[s]] = mx6[s];
            sm_s [wn * ROWS_CTA + rowL[s]] = s6[s];
        }
    }
    __syncthreads();
    if (tid < ROWS_CTA) {
        float m = sm_mx[tid], ss = sm_s[tid];
        merge_ms(m, ss, sm_mx[ROWS_CTA + tid], sm_s[ROWS_CTA + tid]);
        g_mxPart[(size_t)(row0 + tid) * PAIRS + pair] = m;
        g_sPart [(size_t)(row0 + tid) * PAIRS + pair] = ss;
    }
}

// ============ Kernel 2: per-row merge partials + positive-term sums ============
__global__ void __launch_bounds__(256)
pass2_kernel(const int* __restrict__ label)
{
    __shared__ float  rm[256], rs[256];
    __shared__ double rd1[256], rd2[256];
    const int n = blockIdx.x;
    const int t = threadIdx.x;
    const int cval = label[n % C_CLS];

    float m = -1e30f, s = 0.0f;
    if (t < PAIRS) { m = g_mxPart[(size_t)n * PAIRS + t]; s = g_sPart[(size_t)n * PAIRS + t]; }
    rm[t] = m; rs[t] = s;
    __syncthreads();
    for (int off = 128; off > 0; off >>= 1) {
        if (t < off) {
            float mm = rm[t], sv = rs[t];
            merge_ms(mm, sv, rm[t + off], rs[t + off]);
            rm[t] = mm; rs[t] = sv;
        }
        __syncthreads();
    }
    const float MX = rm[0], S = rs[0];
    const float logS = __logf(S);

    double t1 = 0.0, t2 = 0.0;
    const float* Pr = g_P + (size_t)n * QS;
    for (int j = t; j < QS; j += 256) {
        if (cval == 0 && j == n) continue;       // self-contrast removal
        float x = Pr[j] - MX;
        t1 += (double)x;
        float term;
        if (x > 80.0f)             term = x;
        else if (x < logS - 15.0f) term = logS;
        else                       term = __logf(__expf(x) + S);
        t2 += (double)term;
    }
    rd1[t] = t1; rd2[t] = t2;
    __syncthreads();
    for (int off = 128; off > 0; off >>= 1) {
        if (t < off) { rd1[t] += rd1[t + off]; rd2[t] += rd2[t + off]; }
        __syncthreads();
    }
    if (t == 0) {
        double Pn = (cval == 0) ? (double)(QS - 1) : (double)QS;
        g_mlpp[n] = (float)((rd1[0] - rd2[0]) / Pn);
    }
}

// ============ Kernel 3: final scalar ============
__global__ void pass3_kernel(float* __restrict__ out)
{
    __shared__ double r[64];
    int t = threadIdx.x;
    double v = 0.0;
    for (int i = t; i < N_ROWS; i += 64) v += (double)g_mlpp[i];
    r[t] = v; __syncthreads();
    for (int off = 32; off > 0; off >>= 1) {
        if (t < off) r[t] += r[t + off];
        __syncthreads();
    }
    if (t == 0) out[0] = (float)(-(r[0] / (double)N_ROWS) * 0.5);
}

extern "C" void kernel_launch(void* const* d_in, const int* in_sizes, int n_in,
                              void* d_out, int out_size)
{
    const float* feat  = (const float*)d_in[0];
    const int*   label = (const int*)d_in[1];
    const float* queue = (const float*)d_in[2];
    float* out = (float*)d_out;

    cudaFuncSetAttribute(gemm_stats_kernel,
                         cudaFuncAttributeMaxDynamicSharedMemorySize, SMEM_BYTES);
    gemm_stats_kernel<<<GRID1, 128, SMEM_BYTES>>>(feat, label, queue);
    pass2_kernel<<<N_ROWS, 256>>>(label);
    pass3_kernel<<<1, 64>>>(out);
}

// round 16
// speedup vs baseline: 1.4297x; 1.1069x over previous
#include <cuda_runtime.h>
#include <cuda_bf16.h>
#include <cstdint>

#define C_CLS   19
#define V_VIEWS 10
#define QS      8192
#define M_TOT   311296
#define N_ROWS  190
#define N_PAD   192
#define INV_T   (1.0f/0.07f)
#define L2E     1.44269504f

#define NCTA      148
#define TILE_COLS 64
#define TOT_TILES (M_TOT / TILE_COLS)    // 4864

// packed A: [rg(12)][kk(16)][lane(32)][4 words] = 24576 u32 = 96 KB
#define A_WORDS   (12*16*32*4)
// packed B: [cg(8)][kk(16)][lane(32)][2 words] = 8192 u32 = 32 KB, x2 buffers
#define B_WORDS   (8*16*32*2)
#define STATS_W   (2*N_PAD*2)
#define SMEM_BYTES ((A_WORDS + 2*B_WORDS + STATS_W)*4)   // 166912 B

__device__ float g_P [N_ROWS * QS];
__device__ float g_mx[N_ROWS * NCTA];
__device__ float g_s [N_ROWS * NCTA];
__device__ float g_mlpp[N_ROWS];

__device__ __forceinline__ float fexp2(float x) {
    float y; asm("ex2.approx.ftz.f32 %0, %1;" : "=f"(y) : "f"(x)); return y;
}
__device__ __forceinline__ uint32_t pack2(float lo, float hi) {
    uint32_t r; asm("cvt.rn.bf16x2.f32 %0, %1, %2;" : "=r"(r) : "f"(hi), "f"(lo)); return r;
}
__device__ __forceinline__ void mma_bf16(float& d0, float& d1, float& d2, float& d3,
                                         uint32_t a0, uint32_t a1, uint32_t a2, uint32_t a3,
                                         uint32_t b0, uint32_t b1) {
    asm("mma.sync.aligned.m16n8k16.row.col.f32.bf16.bf16.f32 "
        "{%0,%1,%2,%3}, {%4,%5,%6,%7}, {%8,%9}, {%0,%1,%2,%3};\n"
        : "+f"(d0), "+f"(d1), "+f"(d2), "+f"(d3)
        : "r"(a0), "r"(a1), "r"(a2), "r"(a3), "r"(b0), "r"(b1));
}
__device__ __forceinline__ void upd_ms(float& m, float& s, float d) {
    if (d > m) { s = s * fexp2((m - d) * L2E) + 1.0f; m = d; }
    else if (d - m > -30.0f) { s += fexp2((d - m) * L2E); }
}
__device__ __forceinline__ void merge_ms(float& m, float& s, float mo, float so) {
    float nm = fmaxf(m, mo);
    s = s * fexp2((m - nm) * L2E) + so * fexp2((mo - nm) * L2E);
    m = nm;
}
// packed-A word index for local row r (0..191), k-pair word w (0..127)
__device__ __forceinline__ int a_addr(int r, int w) {
    int rg = r >> 4, rr = r & 15;
    int kk = w >> 3, ww = w & 7;
    int lane = (rr & 7) * 4 + (ww & 3);
    int j = (rr >> 3) + 2 * (ww >> 2);
    return ((rg * 16 + kk) * 32 + lane) * 4 + j;
}
// store 2 ksteps (kk0, kk0+1) of col c from 8 staged float4 (32 k values)
__device__ __forceinline__ void sts_half2(uint32_t* Bst, const float4* st, int c, int kk0) {
    const int cg = c >> 3;
    const int xbit = (c >> 2) & 1;
    const int crow = (c & 7) * 2;
    #pragma unroll
    for (int jj = 0; jj < 2; jj++) {
        int kk = kk0 + jj;
        uint32_t base = (uint32_t)(cg * 16 + kk) * 64;
        const float4* q = st + jj * 4;
        uint32_t u0 = pack2(q[0].x, q[0].y);
        uint32_t u1 = pack2(q[2].x, q[2].y);
        uint32_t u2 = pack2(q[0].z, q[0].w);
        uint32_t u3 = pack2(q[2].z, q[2].w);
        uint32_t u4 = pack2(q[1].x, q[1].y);
        uint32_t u5 = pack2(q[3].x, q[3].y);
        uint32_t u6 = pack2(q[1].z, q[1].w);
        uint32_t u7 = pack2(q[3].z, q[3].w);
        *(uint4*)(Bst + base + (uint32_t)(((crow + 0) ^ xbit) << 2)) = make_uint4(u0,u1,u2,u3);
        *(uint4*)(Bst + base + (uint32_t)(((crow + 1) ^ xbit) << 2)) = make_uint4(u4,u5,u6,u7);
    }
}

// ============ Kernel 1: fused bf16-MMA GEMM + online neg (max,sumexp) ============
// grid = 148 (one wave), 256 threads, 8 warps = 4m x 2n, warp tile 48x32
__global__ void __launch_bounds__(256, 1)
gemm_stats_kernel(const float* __restrict__ feat,
                  const int*   __restrict__ label,
                  const float* __restrict__ queue)
{
    extern __shared__ uint32_t sm[];
    uint32_t* AsP = sm;
    uint32_t* Bs0 = sm + A_WORDS;
    uint32_t* Bs1 = sm + A_WORDS + B_WORDS;
    float*    sm_mx = (float*)(sm + A_WORDS + 2*B_WORDS);
    float*    sm_s  = sm_mx + 2 * N_PAD;
    __shared__ int slab[C_CLS];

    const int tid  = threadIdx.x;
    const int lane = tid & 31;
    const int warp = tid >> 5;
    const int wm   = warp & 3;          // 4 m-warps (48 rows each)
    const int wn   = warp >> 2;         // 2 n-warps (32 cols each)
    const int g    = lane >> 2;
    const int tig  = lane & 3;
    const int cta  = blockIdx.x;
    const int nt   = (TOT_TILES - cta + NCTA - 1) / NCTA;

    if (tid < C_CLS) slab[tid] = label[tid];

    // ---- fill packed A: feat/T as bf16 fragments (rows >=190 zero) ----
    {
        const float4* f4 = (const float4*)feat;
        for (int i = tid; i < N_PAD * 64; i += 256) {
            int r = i >> 6, wp = i & 63;
            uint32_t v0 = 0u, v1 = 0u;
            if (r < N_ROWS) {
                int cc = r % C_CLS, vv = r / C_CLS;
                float4 x = f4[(cc * V_VIEWS + vv) * 64 + wp];
                v0 = pack2(x.x * INV_T, x.y * INV_T);
                v1 = pack2(x.z * INV_T, x.w * INV_T);
            }
            AsP[a_addr(r, wp * 2)]     = v0;
            AsP[a_addr(r, wp * 2 + 1)] = v1;
        }
    }

    const int c    = tid & 63;
    const int part = tid >> 6;          // 4 k-quarters of 64 k each
    const float4* q4 = (const float4*)queue;
    const int loff = ((((lane >> 1) ^ ((lane >> 4) & 1)) << 2) + (lane & 1) * 2);

    // ---- prologue: stage tile(cta) into Bs0 ----
    {
        float4 st[8];
        const float4* p = q4 + (size_t)(cta * TILE_COLS + c) * 64 + part * 16;
        #pragma unroll
        for (int u = 0; u < 8; u++) st[u] = p[u];
        sts_half2(Bs0, st, c, part * 4);
        #pragma unroll
        for (int u = 0; u < 8; u++) st[u] = p[8 + u];
        sts_half2(Bs0, st, c, part * 4 + 2);
    }
    __syncthreads();

    // ---- per-lane slots: 6 rows per lane ----
    float mx6[6], s6[6];
    int   rowL[6], cls6[6];
    #pragma unroll
    for (int s = 0; s < 6; s++) {
        int mi = s >> 1, h = s & 1;
        int rl = wm * 48 + mi * 16 + g + h * 8;
        rowL[s] = rl;
        cls6[s] = slab[rl % C_CLS];
        mx6[s] = -1e30f; s6[s] = 0.0f;
    }

    int tcur = cta;
    for (int it = 0; it < nt; it++, tcur += NCTA) {
        uint32_t* Bc = (it & 1) ? Bs1 : Bs0;
        uint32_t* Bo = (it & 1) ? Bs0 : Bs1;
        const bool nx = (it + 1 < nt);
        const float4* np4 = q4 + (size_t)((tcur + NCTA) * TILE_COLS + c) * 64 + part * 16;

        float4 st[8];
        if (nx) {
            #pragma unroll
            for (int u = 0; u < 8; u++) st[u] = np4[u];
        }

        float acc[3][4][4];
        #pragma unroll
        for (int mi = 0; mi < 3; mi++)
            #pragma unroll
            for (int nj = 0; nj < 4; nj++)
                #pragma unroll
                for (int v = 0; v < 4; v++) acc[mi][nj][v] = 0.0f;

        // ===== ksteps 0..7 on Bc =====
        #pragma unroll
        for (int kk = 0; kk < 8; kk++) {
            uint2 b[4];
            #pragma unroll
            for (int nj = 0; nj < 4; nj++)
                b[nj] = *(const uint2*)(Bc + ((wn * 4 + nj) * 16 + kk) * 64 + loff);
            #pragma unroll
            for (int mi = 0; mi < 3; mi++) {
                uint4 a = *(const uint4*)(AsP + (((wm * 3 + mi) * 16 + kk) * 32 + lane) * 4);
                #pragma unroll
                for (int nj = 0; nj < 4; nj++)
                    mma_bf16(acc[mi][nj][0], acc[mi][nj][1], acc[mi][nj][2], acc[mi][nj][3],
                             a.x, a.y, a.z, a.w, b[nj].x, b[nj].y);
            }
        }

        if (nx) {
            sts_half2(Bo, st, c, part * 4);
            #pragma unroll
            for (int u = 0; u < 8; u++) st[u] = np4[8 + u];
        }

        // ===== ksteps 8..15 on Bc =====
        #pragma unroll
        for (int kk = 8; kk < 16; kk++) {
            uint2 b[4];
            #pragma unroll
            for (int nj = 0; nj < 4; nj++)
                b[nj] = *(const uint2*)(Bc + ((wn * 4 + nj) * 16 + kk) * 64 + loff);
            #pragma unroll
            for (int mi = 0; mi < 3; mi++) {
                uint4 a = *(const uint4*)(AsP + (((wm * 3 + mi) * 16 + kk) * 32 + lane) * 4);
                #pragma unroll
                for (int nj = 0; nj < 4; nj++)
                    mma_bf16(acc[mi][nj][0], acc[mi][nj][1], acc[mi][nj][2], acc[mi][nj][3],
                             a.x, a.y, a.z, a.w, b[nj].x, b[nj].y);
            }
        }

        if (nx) sts_half2(Bo, st, c, part * 4 + 2);

        // ===== epilogue for tile tcur =====
        const int qrow = tcur >> 7;                          // class of this tile
        const int cb   = ((tcur & 127) << 6) + wn * 32 + tig * 2;  // col in class block
        #pragma unroll
        for (int s = 0; s < 6; s++) {
            const int mi = s >> 1, h2 = s & 1;
            if (cls6[s] == qrow) {
                if (rowL[s] < N_ROWS) {
                    float* pp = g_P + (size_t)rowL[s] * QS + cb;
                    #pragma unroll
                    for (int nj = 0; nj < 4; nj++)
                        *(float2*)(pp + nj * 8) =
                            make_float2(acc[mi][nj][h2 * 2], acc[mi][nj][h2 * 2 + 1]);
                }
            } else {
                #pragma unroll
                for (int nj = 0; nj < 4; nj++) {
                    upd_ms(mx6[s], s6[s], acc[mi][nj][h2 * 2]);
                    upd_ms(mx6[s], s6[s], acc[mi][nj][h2 * 2 + 1]);
                }
            }
        }
        __syncthreads();
    }

    // ---- reduce stats: quad shfl -> smem per wn -> merge -> global partials ----
    #pragma unroll
    for (int s = 0; s < 6; s++) {
        #pragma unroll
        for (int off = 1; off <= 2; off <<= 1) {
            float mo = __shfl_xor_sync(0xffffffffu, mx6[s], off);
            float so = __shfl_xor_sync(0xffffffffu, s6[s], off);
            merge_ms(mx6[s], s6[s], mo, so);
        }
    }
    if (tig == 0) {
        #pragma unroll
        for (int s = 0; s < 6; s++) {
            sm_mx[wn * N_PAD + rowL[s]] = mx6[s];
            sm_s [wn * N_PAD + rowL[s]] = s6[s];
        }
    }
    __syncthreads();
    if (tid < N_ROWS) {
        float m = sm_mx[tid], ss = sm_s[tid];
        merge_ms(m, ss, sm_mx[N_PAD + tid], sm_s[N_PAD + tid]);
        g_mx[(size_t)tid * NCTA + cta] = m;
        g_s [(size_t)tid * NCTA + cta] = ss;
    }
}

// ============ Kernel 2: per-row merge partials + positive-term sums ============
__global__ void __launch_bounds__(256)
pass2_kernel(const int* __restrict__ label)
{
    __shared__ float  rm[256], rs[256];
    __shared__ double rd1[256], rd2[256];
    const int n = blockIdx.x;
    const int t = threadIdx.x;
    const int cval = label[n % C_CLS];

    float m = -1e30f, s = 0.0f;
    if (t < NCTA) { m = g_mx[(size_t)n * NCTA + t]; s = g_s[(size_t)n * NCTA + t]; }
    rm[t] = m; rs[t] = s;
    __syncthreads();
    for (int off = 128; off > 0; off >>= 1) {
        if (t < off) {
            float mm = rm[t], sv = rs[t];
            merge_ms(mm, sv, rm[t + off], rs[t + off]);
            rm[t] = mm; rs[t] = sv;
        }
        __syncthreads();
    }
    const float MX = rm[0], S = rs[0];
    const float logS = __logf(S);

    double t1 = 0.0, t2 = 0.0;
    const float* Pr = g_P + (size_t)n * QS;
    for (int j = t; j < QS; j += 256) {
        if (cval == 0 && j == n) continue;       // self-contrast removal
        float x = Pr[j] - MX;
        t1 += (double)x;
        float term;
        if (x > 80.0f)             term = x;
        else if (x < logS - 15.0f) term = logS;
        else                       term = __logf(__expf(x) + S);
        t2 += (double)term;
    }
    rd1[t] = t1; rd2[t] = t2;
    __syncthreads();
    for (int off = 128; off > 0; off >>= 1) {
        if (t < off) { rd1[t] += rd1[t + off]; rd2[t] += rd2[t + off]; }
        __syncthreads();
    }
    if (t == 0) {
        double Pn = (cval == 0) ? (double)(QS - 1) : (double)QS;
        g_mlpp[n] = (float)((rd1[0] - rd2[0]) / Pn);
    }
}

// ============ Kernel 3: final scalar ============
__global__ void pass3_kernel(float* __restrict__ out)
{
    __shared__ double r[64];
    int t = threadIdx.x;
    double v = 0.0;
    for (int i = t; i < N_ROWS; i += 64) v += (double)g_mlpp[i];
    r[t] = v; __syncthreads();
    for (int off = 32; off > 0; off >>= 1) {
        if (t < off) r[t] += r[t + off];
        __syncthreads();
    }
    if (t == 0) out[0] = (float)(-(r[0] / (double)N_ROWS) * 0.5);
}

extern "C" void kernel_launch(void* const* d_in, const int* in_sizes, int n_in,
                              void* d_out, int out_size)
{
    const float* feat  = (const float*)d_in[0];
    const int*   label = (const int*)d_in[1];
    const float* queue = (const float*)d_in[2];
    float* out = (float*)d_out;

    cudaFuncSetAttribute(gemm_stats_kernel,
                         cudaFuncAttributeMaxDynamicSharedMemorySize, SMEM_BYTES);
    gemm_stats_kernel<<<NCTA, 256, SMEM_BYTES>>>(feat, label, queue);
    pass2_kernel<<<N_ROWS, 256>>>(label);
    pass3_kernel<<<1, 64>>>(out);
}

// round 17
// speedup vs baseline: 1.4979x; 1.0477x over previous
#include <cuda_runtime.h>
#include <cuda_bf16.h>
#include <cstdint>

#define C_CLS   19
#define V_VIEWS 10
#define QS      8192
#define M_TOT   311296
#define N_ROWS  190
#define N_PAD   192
#define INV_T   (1.0f/0.07f)
#define L2E     1.44269504f

#define NCTA      148
#define TILE_COLS 64
#define TOT_TILES (M_TOT / TILE_COLS)    // 4864

// packed A: [rg(12)][kk(16)][lane(32)][4 words] = 24576 u32 = 96 KB
#define A_WORDS   (12*16*32*4)
// packed B: [cg(8)][kk(16)][lane(32)][2 words] = 8192 u32 = 32 KB, x2 buffers
#define B_WORDS   (8*16*32*2)
#define STATS_W   (2*N_PAD*2)
#define SMEM_BYTES ((A_WORDS + 2*B_WORDS + STATS_W)*4)   // 166912 B

__device__ float g_P [N_ROWS * QS];
__device__ float g_mx[N_ROWS * NCTA];
__device__ float g_s [N_ROWS * NCTA];
__device__ float g_mlpp[N_ROWS];

__device__ __forceinline__ float fexp2(float x) {
    float y; asm("ex2.approx.ftz.f32 %0, %1;" : "=f"(y) : "f"(x)); return y;
}
__device__ __forceinline__ uint32_t pack2(float lo, float hi) {
    uint32_t r; asm("cvt.rn.bf16x2.f32 %0, %1, %2;" : "=r"(r) : "f"(hi), "f"(lo)); return r;
}
__device__ __forceinline__ void mma_bf16(float& d0, float& d1, float& d2, float& d3,
                                         uint32_t a0, uint32_t a1, uint32_t a2, uint32_t a3,
                                         uint32_t b0, uint32_t b1) {
    asm("mma.sync.aligned.m16n8k16.row.col.f32.bf16.bf16.f32 "
        "{%0,%1,%2,%3}, {%4,%5,%6,%7}, {%8,%9}, {%0,%1,%2,%3};\n"
        : "+f"(d0), "+f"(d1), "+f"(d2), "+f"(d3)
        : "r"(a0), "r"(a1), "r"(a2), "r"(a3), "r"(b0), "r"(b1));
}
__device__ __forceinline__ void upd_ms(float& m, float& s, float d) {
    if (d > m) { s = s * fexp2((m - d) * L2E) + 1.0f; m = d; }
    else if (d - m > -30.0f) { s += fexp2((d - m) * L2E); }
}
__device__ __forceinline__ void merge_ms(float& m, float& s, float mo, float so) {
    float nm = fmaxf(m, mo);
    s = s * fexp2((m - nm) * L2E) + so * fexp2((mo - nm) * L2E);
    m = nm;
}
// packed-A word index for local row r (0..191), k-pair word w (0..127)
__device__ __forceinline__ int a_addr(int r, int w) {
    int rg = r >> 4, rr = r & 15;
    int kk = w >> 3, ww = w & 7;
    int lane = (rr & 7) * 4 + (ww & 3);
    int j = (rr >> 3) + 2 * (ww >> 2);
    return ((rg * 16 + kk) * 32 + lane) * 4 + j;
}
// store 2 ksteps (kk0, kk0+1) of col c from 8 staged float4 (32 k values)
__device__ __forceinline__ void sts_half2(uint32_t* Bst, const float4* st, int c, int kk0) {
    const int cg = c >> 3;
    const int xbit = (c >> 2) & 1;
    const int crow = (c & 7) * 2;
    #pragma unroll
    for (int jj = 0; jj < 2; jj++) {
        int kk = kk0 + jj;
        uint32_t base = (uint32_t)(cg * 16 + kk) * 64;
        const float4* q = st + jj * 4;
        uint32_t u0 = pack2(q[0].x, q[0].y);
        uint32_t u1 = pack2(q[2].x, q[2].y);
        uint32_t u2 = pack2(q[0].z, q[0].w);
        uint32_t u3 = pack2(q[2].z, q[2].w);
        uint32_t u4 = pack2(q[1].x, q[1].y);
        uint32_t u5 = pack2(q[3].x, q[3].y);
        uint32_t u6 = pack2(q[1].z, q[1].w);
        uint32_t u7 = pack2(q[3].z, q[3].w);
        *(uint4*)(Bst + base + (uint32_t)(((crow + 0) ^ xbit) << 2)) = make_uint4(u0,u1,u2,u3);
        *(uint4*)(Bst + base + (uint32_t)(((crow + 1) ^ xbit) << 2)) = make_uint4(u4,u5,u6,u7);
    }
}
// full 64-k store: st[16] float4 -> 4 ksteps starting at part*4
__device__ __forceinline__ void sts_full(uint32_t* Bst, const float4* st, int c, int part) {
    sts_half2(Bst, st,     c, part * 4);
    sts_half2(Bst, st + 8, c, part * 4 + 2);
}

// ============ Kernel 1: fused bf16-MMA GEMM + online neg (max,sumexp) ============
// grid = 148 (one wave), 256 threads, 8 warps = 4m x 2n, warp tile 48x32
__global__ void __launch_bounds__(256, 1)
gemm_stats_kernel(const float* __restrict__ feat,
                  const int*   __restrict__ label,
                  const float* __restrict__ queue)
{
    extern __shared__ uint32_t sm[];
    uint32_t* AsP = sm;
    uint32_t* Bs0 = sm + A_WORDS;
    uint32_t* Bs1 = sm + A_WORDS + B_WORDS;
    float*    sm_mx = (float*)(sm + A_WORDS + 2*B_WORDS);
    float*    sm_s  = sm_mx + 2 * N_PAD;
    __shared__ int slab[C_CLS];

    const int tid  = threadIdx.x;
    const int lane = tid & 31;
    const int warp = tid >> 5;
    const int wm   = warp & 3;          // 4 m-warps (48 rows each)
    const int wn   = warp >> 2;         // 2 n-warps (32 cols each)
    const int g    = lane >> 2;
    const int tig  = lane & 3;
    const int cta  = blockIdx.x;
    const int nt   = (TOT_TILES - cta + NCTA - 1) / NCTA;

    if (tid < C_CLS) slab[tid] = label[tid];

    // ---- fill packed A: feat/T as bf16 fragments (rows >=190 zero) ----
    {
        const float4* f4 = (const float4*)feat;
        for (int i = tid; i < N_PAD * 64; i += 256) {
            int r = i >> 6, wp = i & 63;
            uint32_t v0 = 0u, v1 = 0u;
            if (r < N_ROWS) {
                int cc = r % C_CLS, vv = r / C_CLS;
                float4 x = f4[(cc * V_VIEWS + vv) * 64 + wp];
                v0 = pack2(x.x * INV_T, x.y * INV_T);
                v1 = pack2(x.z * INV_T, x.w * INV_T);
            }
            AsP[a_addr(r, wp * 2)]     = v0;
            AsP[a_addr(r, wp * 2 + 1)] = v1;
        }
    }

    const int c    = tid & 63;
    const int part = tid >> 6;          // 4 k-quarters of 64 k each
    const float4* q4 = (const float4*)queue;
    const int loff = ((((lane >> 1) ^ ((lane >> 4) & 1)) << 2) + (lane & 1) * 2);

    // ---- per-lane slots: 6 rows per lane ----
    float mx6[6], s6[6];
    int   rowL[6], cls6[6];
    #pragma unroll
    for (int s = 0; s < 6; s++) {
        int mi = s >> 1, h = s & 1;
        int rl = wm * 48 + mi * 16 + g + h * 8;
        rowL[s] = rl;
        cls6[s] = slab[rl % C_CLS];
        mx6[s] = -1e30f; s6[s] = 0.0f;
    }

    // ---- prologue: tile0 -> Bs0; tile1 staged in regs ----
    float4 st[16];
    {
        const float4* p = q4 + (size_t)(cta * TILE_COLS + c) * 64 + part * 16;
        #pragma unroll
        for (int u = 0; u < 16; u++) st[u] = p[u];
        sts_full(Bs0, st, c, part);
    }
    __syncthreads();
    if (nt > 1) {
        const float4* p = q4 + (size_t)((cta + NCTA) * TILE_COLS + c) * 64 + part * 16;
        #pragma unroll
        for (int u = 0; u < 16; u++) st[u] = p[u];
    }

    int tcur = cta;
    for (int it = 0; it < nt; it++, tcur += NCTA) {
        uint32_t* Bc = (it & 1) ? Bs1 : Bs0;
        uint32_t* Bn = (it & 1) ? Bs0 : Bs1;

        float acc[3][4][4];
        #pragma unroll
        for (int mi = 0; mi < 3; mi++)
            #pragma unroll
            for (int nj = 0; nj < 4; nj++)
                #pragma unroll
                for (int v = 0; v < 4; v++) acc[mi][nj][v] = 0.0f;

        // ===== full 16-kstep MMA block on Bc (st LDG from prev iter in flight) =====
        #pragma unroll
        for (int kk = 0; kk < 16; kk++) {
            uint2 b[4];
            #pragma unroll
            for (int nj = 0; nj < 4; nj++)
                b[nj] = *(const uint2*)(Bc + ((wn * 4 + nj) * 16 + kk) * 64 + loff);
            #pragma unroll
            for (int mi = 0; mi < 3; mi++) {
                uint4 a = *(const uint4*)(AsP + (((wm * 3 + mi) * 16 + kk) * 32 + lane) * 4);
                #pragma unroll
                for (int nj = 0; nj < 4; nj++)
                    mma_bf16(acc[mi][nj][0], acc[mi][nj][1], acc[mi][nj][2], acc[mi][nj][3],
                             a.x, a.y, a.z, a.w, b[nj].x, b[nj].y);
            }
        }

        // ===== epilogue for tile tcur (acc-only; overlaps in-flight LDG) =====
        const int qrow = tcur >> 7;
        const int cb   = ((tcur & 127) << 6) + wn * 32 + tig * 2;
        #pragma unroll
        for (int s = 0; s < 6; s++) {
            const int mi = s >> 1, h2 = s & 1;
            if (cls6[s] == qrow) {
                if (rowL[s] < N_ROWS) {
                    float* pp = g_P + (size_t)rowL[s] * QS + cb;
                    #pragma unroll
                    for (int nj = 0; nj < 4; nj++)
                        *(float2*)(pp + nj * 8) =
                            make_float2(acc[mi][nj][h2 * 2], acc[mi][nj][h2 * 2 + 1]);
                }
            } else {
                #pragma unroll
                for (int nj = 0; nj < 4; nj++) {
                    upd_ms(mx6[s], s6[s], acc[mi][nj][h2 * 2]);
                    upd_ms(mx6[s], s6[s], acc[mi][nj][h2 * 2 + 1]);
                }
            }
        }

        // ===== store tile it+1 (regs -> Bn), then prefetch tile it+2 =====
        if (it + 1 < nt) {
            sts_full(Bn, st, c, part);
            if (it + 2 < nt) {
                const float4* p = q4
                    + (size_t)((tcur + 2 * NCTA) * TILE_COLS + c) * 64 + part * 16;
                #pragma unroll
                for (int u = 0; u < 16; u++) st[u] = p[u];
            }
        }
        __syncthreads();
    }

    // ---- reduce stats: quad shfl -> smem per wn -> merge -> global partials ----
    #pragma unroll
    for (int s = 0; s < 6; s++) {
        #pragma unroll
        for (int off = 1; off <= 2; off <<= 1) {
            float mo = __shfl_xor_sync(0xffffffffu, mx6[s], off);
            float so = __shfl_xor_sync(0xffffffffu, s6[s], off);
            merge_ms(mx6[s], s6[s], mo, so);
        }
    }
    if (tig == 0) {
        #pragma unroll
        for (int s = 0; s < 6; s++) {
            sm_mx[wn * N_PAD + rowL[s]] = mx6[s];
            sm_s [wn * N_PAD + rowL[s]] = s6[s];
        }
    }
    __syncthreads();
    if (tid < N_ROWS) {
        float m = sm_mx[tid], ss = sm_s[tid];
        merge_ms(m, ss, sm_mx[N_PAD + tid], sm_s[N_PAD + tid]);
        g_mx[(size_t)tid * NCTA + cta] = m;
        g_s [(size_t)tid * NCTA + cta] = ss;
    }
}

// ============ Kernel 2: per-row merge partials + positive-term sums ============
__global__ void __launch_bounds__(256)
pass2_kernel(const int* __restrict__ label)
{
    __shared__ float  rm[256], rs[256];
    __shared__ double rd1[256], rd2[256];
    const int n = blockIdx.x;
    const int t = threadIdx.x;
    const int cval = label[n % C_CLS];

    float m = -1e30f, s = 0.0f;
    if (t < NCTA) { m = g_mx[(size_t)n * NCTA + t]; s = g_s[(size_t)n * NCTA + t]; }
    rm[t] = m; rs[t] = s;
    __syncthreads();
    for (int off = 128; off > 0; off >>= 1) {
        if (t < off) {
            float mm = rm[t], sv = rs[t];
            merge_ms(mm, sv, rm[t + off], rs[t + off]);
            rm[t] = mm; rs[t] = sv;
        }
        __syncthreads();
    }
    const float MX = rm[0], S = rs[0];
    const float logS = __logf(S);

    double t1 = 0.0, t2 = 0.0;
    const float* Pr = g_P + (size_t)n * QS;
    for (int j = t; j < QS; j += 256) {
        if (cval == 0 && j == n) continue;       // self-contrast removal
        float x = Pr[j] - MX;
        t1 += (double)x;
        float term;
        if (x > 80.0f)             term = x;
        else if (x < logS - 15.0f) term = logS;
        else                       term = __logf(__expf(x) + S);
        t2 += (double)term;
    }
    rd1[t] = t1; rd2[t] = t2;
    __syncthreads();
    for (int off = 128; off > 0; off >>= 1) {
        if (t < off) { rd1[t] += rd1[t + off]; rd2[t] += rd2[t + off]; }
        __syncthreads();
    }
    if (t == 0) {
        double Pn = (cval == 0) ? (double)(QS - 1) : (double)QS;
        g_mlpp[n] = (float)((rd1[0] - rd2[0]) / Pn);
    }
}

// ============ Kernel 3: final scalar ============
__global__ void pass3_kernel(float* __restrict__ out)
{
    __shared__ double r[64];
    int t = threadIdx.x;
    double v = 0.0;
    for (int i = t; i < N_ROWS; i += 64) v += (double)g_mlpp[i];
    r[t] = v; __syncthreads();
    for (int off = 32; off > 0; off >>= 1) {
        if (t < off) r[t] += r[t + off];
        __syncthreads();
    }
    if (t == 0) out[0] = (float)(-(r[0] / (double)N_ROWS) * 0.5);
}

extern "C" void kernel_launch(void* const* d_in, const int* in_sizes, int n_in,
                              void* d_out, int out_size)
{
    const float* feat  = (const float*)d_in[0];
    const int*   label = (const int*)d_in[1];
    const float* queue = (const float*)d_in[2];
    float* out = (float*)d_out;

    cudaFuncSetAttribute(gemm_stats_kernel,
                         cudaFuncAttributeMaxDynamicSharedMemorySize, SMEM_BYTES);
    gemm_stats_kernel<<<NCTA, 256, SMEM_BYTES>>>(feat, label, queue);
    pass2_kernel<<<N_ROWS, 256>>>(label);
    pass3_kernel<<<1, 64>>>(out);
}